// round 2
// baseline (speedup 1.0000x reference)
#include <cuda_runtime.h>
#include <math.h>

// Problem constants
#define S_STAGES 3
#define BATCH    32
#define NPRIOR   2000
#define LANES    4
#define DFEAT    78          // 2 + 4 + 72
#define NOFF     72
#define SB       (S_STAGES * BATCH)   // 96
#define IMG_W_F  800.0f
#define IMG_W1_F 799.0f

// Scratch (device globals — no allocation allowed)
__device__ int   g_rows[2 * SB * LANES];
__device__ float g_reg [2 * SB * LANES];
__device__ float g_iou [2 * SB * LANES];
__device__ float g_cls [2 * NPRIOR];

// ---------------------------------------------------------------------------
// Kernel A: cost + greedy assignment + reg/iou per (branch, s, b)
// ---------------------------------------------------------------------------
__global__ __launch_bounds__(256) void assign_kernel(
    const float* __restrict__ predA,
    const float* __restrict__ predB,
    const float* __restrict__ gt)
{
    const int sb     = blockIdx.x;           // 0..95  (s*32 + b)
    const int branch = blockIdx.y;           // 0..1
    const float* __restrict__ pred = branch ? predB : predA;
    const int b = sb & 31;
    const float* prow_base = pred + (size_t)sb * NPRIOR * DFEAT;

    __shared__ float sh_gt[LANES][DFEAT];    // raw gt rows
    __shared__ float sh_goff[LANES][NOFF];   // gt offsets / 799
    __shared__ float sh_cost[LANES][NPRIOR]; // 32 KB
    __shared__ float s_v[256];
    __shared__ int   s_i[256];
    __shared__ int   rows_sh[LANES];

    const int tid = threadIdx.x;

    for (int i = tid; i < LANES * DFEAT; i += 256) {
        int l = i / DFEAT, d = i % DFEAT;
        float v = gt[((size_t)b * LANES + l) * DFEAT + d];
        sh_gt[l][d] = v;
        if (d >= 6) sh_goff[l][d - 6] = v / IMG_W1_F;
    }
    __syncthreads();

    const int warp = tid >> 5, lane = tid & 31;
    const unsigned FULL = 0xffffffffu;

    // warp-per-prior: coalesced row loads, shuffle reductions
    for (int n = warp; n < NPRIOR; n += 8) {
        const float* p = prow_base + (size_t)n * DFEAT;
        float v0 = p[lane];
        float v1 = p[lane + 32];
        float v2 = (lane < DFEAT - 64) ? p[lane + 64] : 0.0f;

        float x0 = __shfl_sync(FULL, v0, 0);
        float x1 = __shfl_sync(FULL, v0, 1);

        float g[LANES], o[LANES];
        #pragma unroll
        for (int l = 0; l < LANES; l++) {
            float gg = 0.0f, oo = 0.0f;
            if (lane >= 2 && lane < 6) gg = fabsf(v0 - sh_gt[l][lane]);
            if (lane >= 6)             oo += fabsf(v0 - sh_goff[l][lane - 6]);
            oo += fabsf(v1 - sh_goff[l][lane + 26]);          // dims 32..63 -> off 26..57
            if (lane < DFEAT - 64)     oo += fabsf(v2 - sh_goff[l][lane + 58]); // dims 64..77
            g[l] = gg; o[l] = oo;
        }
        #pragma unroll
        for (int off = 16; off; off >>= 1) {
            #pragma unroll
            for (int l = 0; l < LANES; l++) {
                g[l] += __shfl_xor_sync(FULL, g[l], off);
                o[l] += __shfl_xor_sync(FULL, o[l], off);
            }
        }
        if (lane == 0) {
            float m  = fmaxf(x0, x1);
            float e0 = expf(x0 - m), e1 = expf(x1 - m);
            float score = e1 / (e0 + e1);
            #pragma unroll
            for (int l = 0; l < LANES; l++)
                sh_cost[l][n] = g[l] + o[l] * (1.0f / 72.0f) - score;
        }
    }
    __syncthreads();

    // greedy assignment: 4 sequential argmins, first-index tie-break
    for (int l = 0; l < LANES; l++) {
        float best = INFINITY; int bi = NPRIOR;
        for (int n = tid; n < NPRIOR; n += 256) {
            float c = sh_cost[l][n];
            if (c < best) { best = c; bi = n; }
        }
        s_v[tid] = best; s_i[tid] = bi;
        __syncthreads();
        for (int off = 128; off; off >>= 1) {
            if (tid < off) {
                float vo = s_v[tid + off]; int io = s_i[tid + off];
                if (vo < s_v[tid] || (vo == s_v[tid] && io < s_i[tid])) {
                    s_v[tid] = vo; s_i[tid] = io;
                }
            }
            __syncthreads();
        }
        if (tid == 0) {
            int r = s_i[0];
            rows_sh[l] = r;
            for (int l2 = l + 1; l2 < LANES; l2++) sh_cost[l2][r] = INFINITY;
        }
        __syncthreads();
    }

    // reg + IoU for the 4 matched priors (warp l handles target l)
    if (warp < LANES) {
        const int l = warp;
        const int r = rows_sh[l];
        const float* p = prow_base + (size_t)r * DFEAT;

        float ovrS = 0.0f, uniS = 0.0f;
        for (int k = lane; k < NOFF; k += 32) {
            float rp = p[6 + k] * IMG_W1_F;
            float rt = sh_gt[l][6 + k];
            bool invalid = (rt < 0.0f) || (rt >= IMG_W_F);
            float mn = fminf(rp, rt), mx = fmaxf(rp, rt);
            if (!invalid) {
                ovrS += (mn - mx + 30.0f);
                uniS += (mx - mn + 30.0f);
            }
        }
        #pragma unroll
        for (int off = 16; off; off >>= 1) {
            ovrS += __shfl_xor_sync(FULL, ovrS, off);
            uniS += __shfl_xor_sync(FULL, uniS, off);
        }
        if (lane == 0) {
            const int idx = ((branch * SB + sb) * LANES + l);
            float iou = ovrS / (uniS + 1e-9f);
            g_iou[idx] = (1.0f - iou) * 0.25f;              // (1-iou)/L

            const float sc[4] = {71.0f, IMG_W1_F, 180.0f, 71.0f};
            float ssum = 0.0f;
            #pragma unroll
            for (int j = 0; j < 4; j++) {
                float d  = (p[2 + j] - sh_gt[l][2 + j]) * sc[j];
                float ad = fabsf(d);
                ssum += (ad < 1.0f) ? 0.5f * d * d : ad - 0.5f;
            }
            g_reg[idx]  = ssum * 0.25f * 0.25f;             // mean over 4, /L
            g_rows[idx] = r;
        }
    }
}

// ---------------------------------------------------------------------------
// Kernel B: focal classification loss per prior (both branches)
// ---------------------------------------------------------------------------
__global__ __launch_bounds__(256) void cls_kernel(
    const float* __restrict__ predA,
    const float* __restrict__ predB)
{
    __shared__ int sh_rows[2 * SB * LANES];
    const int tid = threadIdx.x;
    for (int i = tid; i < 2 * SB * LANES; i += 256) sh_rows[i] = g_rows[i];
    __syncthreads();

    const int n = blockIdx.x * 256 + tid;
    if (n >= NPRIOR) return;

    #pragma unroll
    for (int branch = 0; branch < 2; branch++) {
        const float* __restrict__ pred = branch ? predB : predA;
        float acc = 0.0f;
        for (int sb = 0; sb < SB; sb++) {
            const float* p = pred + ((size_t)sb * NPRIOR + n) * DFEAT;
            float x0 = p[0], x1 = p[1];
            const int* r = &sh_rows[(branch * SB + sb) * LANES];
            bool matched = (n == r[0]) | (n == r[1]) | (n == r[2]) | (n == r[3]);
            float m   = fmaxf(x0, x1);
            float lse = m + logf(expf(x0 - m) + expf(x1 - m));
            float logpt = (matched ? x1 : x0) - lse;
            float pt  = expf(logpt);
            float a   = matched ? 0.9f : 0.1f;
            float om  = 1.0f - pt;
            acc += -a * om * om * logpt;
        }
        g_cls[branch * NPRIOR + n] = acc * (1.0f / 96.0f);
    }
}

// ---------------------------------------------------------------------------
// Kernel C: reduce reg/iou, scatter, median(bitonic), final weighted sum
// ---------------------------------------------------------------------------
__global__ __launch_bounds__(1024) void final_kernel(
    const float* __restrict__ diff,
    float* __restrict__ out)
{
    __shared__ float instA[NPRIOR];
    __shared__ float instB[NPRIOR];
    __shared__ float sbuf[2048];
    __shared__ float addv[8];
    __shared__ float red[1024];

    const int tid = threadIdx.x;

    if (tid < 8) {
        int branch = tid >> 2, l = tid & 3;
        float rs = 0.0f, is = 0.0f;
        for (int i = 0; i < SB; i++) {
            rs += g_reg[(branch * SB + i) * LANES + l];
            is += g_iou[(branch * SB + i) * LANES + l];
        }
        addv[tid] = rs * (1.0f / 96.0f) * 0.5f + is * (1.0f / 96.0f) * 2.0f;
    }
    for (int n = tid; n < NPRIOR; n += 1024) {
        instA[n] = g_cls[n]          * 2.0f;   // cls * CLS_W
        instB[n] = g_cls[NPRIOR + n] * 2.0f;
    }
    __syncthreads();

    if (tid < 8) {
        int branch = tid >> 2, l = tid & 3;
        int r = g_rows[(branch * SB + (SB - 1)) * LANES + l];  // rows[-1,-1]
        if (branch == 0) instA[r] += addv[tid];
        else             instB[r] += addv[tid];
    }
    __syncthreads();

    for (int n = tid; n < 2048; n += 1024)
        sbuf[n] = (n < NPRIOR) ? (instA[n] - instB[n]) : INFINITY;
    __syncthreads();

    // bitonic sort ascending (2048 elements)
    for (int k = 2; k <= 2048; k <<= 1) {
        for (int j = k >> 1; j > 0; j >>= 1) {
            for (int i = tid; i < 2048; i += 1024) {
                int ixj = i ^ j;
                if (ixj > i) {
                    bool up = ((i & k) == 0);
                    float a = sbuf[i], c = sbuf[ixj];
                    if ((a > c) == up) { sbuf[i] = c; sbuf[ixj] = a; }
                }
            }
            __syncthreads();
        }
    }

    float delta = 0.5f * (sbuf[999] + sbuf[1000]);   // median of 2000

    float acc = 0.0f;
    for (int n = tid; n < NPRIOR; n += 1024) {
        float dm = (diff[n] + diff[NPRIOR + n] + diff[2 * NPRIOR + n]) * (1.0f / 3.0f);
        acc += (1.0f - dm) * (instA[n] - 0.5f * delta)
             + dm          * (instB[n] + 0.5f * delta);
    }
    red[tid] = acc;
    __syncthreads();
    for (int off = 512; off; off >>= 1) {
        if (tid < off) red[tid] += red[tid + off];
        __syncthreads();
    }
    if (tid == 0) out[0] = red[0];
}

// ---------------------------------------------------------------------------
extern "C" void kernel_launch(void* const* d_in, const int* in_sizes, int n_in,
                              void* d_out, int out_size)
{
    const float* fir  = (const float*)d_in[0];
    const float* sec  = (const float*)d_in[1];
    const float* gt   = (const float*)d_in[2];
    const float* diff = (const float*)d_in[3];
    float* out = (float*)d_out;

    assign_kernel<<<dim3(SB, 2), 256>>>(fir, sec, gt);
    cls_kernel<<<(NPRIOR + 255) / 256, 256>>>(fir, sec);
    final_kernel<<<1, 1024>>>(diff, out);
}

// round 3
// speedup vs baseline: 2.8605x; 2.8605x over previous
#include <cuda_runtime.h>
#include <math.h>

#define S_STAGES 3
#define BATCH    32
#define NPRIOR   2000
#define LANES    4
#define DFEAT    78          // 2 + 4 + 72
#define NOFF     72
#define SB       (S_STAGES * BATCH)   // 96
#define IMG_W_F  800.0f
#define IMG_W1_F 799.0f
#define NSPLIT   10
#define PPB      (NPRIOR / NSPLIT)    // 200 priors per block

// Scratch (device globals — no allocation allowed)
__device__ float g_cost[2 * SB * LANES * NPRIOR];   // 6.1 MB
__device__ float g_cneg[2 * SB * NPRIOR];           // 1.5 MB
__device__ float g_cpos[2 * SB * NPRIOR];           // 1.5 MB
__device__ int   g_rows[2 * SB * LANES];
__device__ float g_reg [2 * SB * LANES];
__device__ float g_iou [2 * SB * LANES];
__device__ float g_cls [2 * NPRIOR];

// ---------------------------------------------------------------------------
// Kernel 1: streaming cost + focal-term computation. Full-chip parallel.
// grid (96, NSPLIT, 2), 256 threads, warp-per-prior.
// ---------------------------------------------------------------------------
__global__ __launch_bounds__(256) void cost_kernel(
    const float* __restrict__ predA,
    const float* __restrict__ predB,
    const float* __restrict__ gt)
{
    const int sb     = blockIdx.x;            // s*32 + b
    const int branch = blockIdx.z;
    const int n0     = blockIdx.y * PPB;
    const float* __restrict__ pred = branch ? predB : predA;
    const int b = sb % BATCH;
    const float* prow_base = pred + (size_t)sb * NPRIOR * DFEAT;

    __shared__ float sh_geo [LANES][4];       // gt dims 2..5
    __shared__ float sh_goff[LANES][NOFF];    // gt offsets / 799

    const int tid = threadIdx.x;
    for (int i = tid; i < LANES * DFEAT; i += 256) {
        int l = i / DFEAT, d = i % DFEAT;
        float v = gt[((size_t)b * LANES + l) * DFEAT + d];
        if (d >= 2 && d < 6) sh_geo[l][d - 2] = v;
        if (d >= 6)          sh_goff[l][d - 6] = v * (1.0f / IMG_W1_F);
    }
    __syncthreads();

    const int warp = tid >> 5, lane = tid & 31;
    const unsigned FULL = 0xffffffffu;
    const size_t bs = (size_t)branch * SB + sb;

    for (int n = n0 + warp; n < n0 + PPB; n += 8) {
        const float* p = prow_base + (size_t)n * DFEAT;
        float v0 = p[lane];
        float v1 = p[lane + 32];
        float v2 = (lane < DFEAT - 64) ? p[lane + 64] : 0.0f;

        float x0 = __shfl_sync(FULL, v0, 0);
        float x1 = __shfl_sync(FULL, v0, 1);

        float c[LANES];
        #pragma unroll
        for (int l = 0; l < LANES; l++) {
            float gg = 0.0f, oo = 0.0f;
            if (lane >= 2 && lane < 6) gg = fabsf(v0 - sh_geo[l][lane - 2]);
            if (lane >= 6)             oo += fabsf(v0 - sh_goff[l][lane - 6]);
            oo += fabsf(v1 - sh_goff[l][lane + 26]);
            if (lane < DFEAT - 64)     oo += fabsf(v2 - sh_goff[l][lane + 58]);
            c[l] = gg + oo * (1.0f / 72.0f);
        }
        #pragma unroll
        for (int off = 16; off; off >>= 1) {
            #pragma unroll
            for (int l = 0; l < LANES; l++)
                c[l] += __shfl_xor_sync(FULL, c[l], off);
        }

        // logits -> score + focal terms (computed on all lanes, written by 4..5)
        float m  = fmaxf(x0, x1);
        float e0 = expf(x0 - m), e1 = expf(x1 - m);
        float denom = e0 + e1;
        float score = e1 / denom;

        if (lane < LANES)
            g_cost[(bs * LANES + lane) * NPRIOR + n] = c[lane] - score;

        float lse   = m + logf(denom);
        float logp0 = x0 - lse, logp1 = x1 - lse;
        float pt0 = e0 / denom, pt1 = score;
        float om0 = 1.0f - pt0, om1 = 1.0f - pt1;
        float cneg = -0.1f * om0 * om0 * logp0;
        float cpos = -0.9f * om1 * om1 * logp1;
        if (lane == 4) g_cneg[bs * NPRIOR + n] = cneg;
        if (lane == 5) g_cpos[bs * NPRIOR + n] = cpos;
    }
}

// ---------------------------------------------------------------------------
// Kernel 2: greedy assignment + reg/iou per (branch, s, b). grid (96, 2).
// ---------------------------------------------------------------------------
__global__ __launch_bounds__(256) void assign_kernel(
    const float* __restrict__ predA,
    const float* __restrict__ predB,
    const float* __restrict__ gt)
{
    const int sb     = blockIdx.x;
    const int branch = blockIdx.y;
    const float* __restrict__ pred = branch ? predB : predA;
    const int b = sb % BATCH;
    const float* prow_base = pred + (size_t)sb * NPRIOR * DFEAT;

    __shared__ float sh_cost[LANES * NPRIOR];   // 32 KB
    __shared__ float sh_gt[LANES][DFEAT];
    __shared__ float s_v[256];
    __shared__ int   s_i[256];
    __shared__ int   rows_sh[LANES];

    const int tid = threadIdx.x;
    const size_t bs = (size_t)branch * SB + sb;

    for (int i = tid; i < LANES * NPRIOR; i += 256)
        sh_cost[i] = g_cost[bs * LANES * NPRIOR + i];
    for (int i = tid; i < LANES * DFEAT; i += 256)
        sh_gt[i / DFEAT][i % DFEAT] = gt[((size_t)b * LANES + i / DFEAT) * DFEAT + i % DFEAT];
    __syncthreads();

    // greedy: 4 sequential argmins, first-index tie-break
    for (int l = 0; l < LANES; l++) {
        float best = INFINITY; int bi = NPRIOR;
        for (int n = tid; n < NPRIOR; n += 256) {
            float cc = sh_cost[l * NPRIOR + n];
            if (cc < best) { best = cc; bi = n; }
        }
        s_v[tid] = best; s_i[tid] = bi;
        __syncthreads();
        for (int off = 128; off; off >>= 1) {
            if (tid < off) {
                float vo = s_v[tid + off]; int io = s_i[tid + off];
                if (vo < s_v[tid] || (vo == s_v[tid] && io < s_i[tid])) {
                    s_v[tid] = vo; s_i[tid] = io;
                }
            }
            __syncthreads();
        }
        if (tid == 0) {
            int r = s_i[0];
            rows_sh[l] = r;
            for (int l2 = l + 1; l2 < LANES; l2++) sh_cost[l2 * NPRIOR + r] = INFINITY;
        }
        __syncthreads();
    }

    const int warp = tid >> 5, lane = tid & 31;
    const unsigned FULL = 0xffffffffu;

    if (warp < LANES) {
        const int l = warp;
        const int r = rows_sh[l];
        const float* p = prow_base + (size_t)r * DFEAT;

        float ovrS = 0.0f, uniS = 0.0f;
        for (int k = lane; k < NOFF; k += 32) {
            float rp = p[6 + k] * IMG_W1_F;
            float rt = sh_gt[l][6 + k];
            bool invalid = (rt < 0.0f) || (rt >= IMG_W_F);
            float mn = fminf(rp, rt), mx = fmaxf(rp, rt);
            if (!invalid) {
                ovrS += (mn - mx + 30.0f);
                uniS += (mx - mn + 30.0f);
            }
        }
        #pragma unroll
        for (int off = 16; off; off >>= 1) {
            ovrS += __shfl_xor_sync(FULL, ovrS, off);
            uniS += __shfl_xor_sync(FULL, uniS, off);
        }
        if (lane == 0) {
            const int idx = (int)(bs * LANES + l);
            float iou = ovrS / (uniS + 1e-9f);
            g_iou[idx] = (1.0f - iou) * 0.25f;

            const float sc[4] = {71.0f, IMG_W1_F, 180.0f, 71.0f};
            float ssum = 0.0f;
            #pragma unroll
            for (int j = 0; j < 4; j++) {
                float d  = (p[2 + j] - sh_gt[l][2 + j]) * sc[j];
                float ad = fabsf(d);
                ssum += (ad < 1.0f) ? 0.5f * d * d : ad - 0.5f;
            }
            g_reg[idx]  = ssum * 0.25f * 0.25f;
            g_rows[idx] = r;
        }
    }
}

// ---------------------------------------------------------------------------
// Kernel 3: cls-neg reduction over sb (L2-resident streaming). grid (8, 2).
// ---------------------------------------------------------------------------
__global__ __launch_bounds__(256) void cls_kernel()
{
    const int n = blockIdx.x * 256 + threadIdx.x;
    const int branch = blockIdx.y;
    if (n >= NPRIOR) return;
    const float* base = g_cneg + (size_t)branch * SB * NPRIOR + n;
    float acc = 0.0f;
    #pragma unroll
    for (int sb = 0; sb < SB; sb++) acc += base[(size_t)sb * NPRIOR];
    g_cls[branch * NPRIOR + n] = acc * (1.0f / 96.0f);
}

// ---------------------------------------------------------------------------
// Kernel 4: corrections + median (bitonic) + final weighted sum. 1 block.
// ---------------------------------------------------------------------------
__global__ __launch_bounds__(1024) void final_kernel(
    const float* __restrict__ diff,
    float* __restrict__ out)
{
    __shared__ float instA[NPRIOR];
    __shared__ float instB[NPRIOR];
    __shared__ float sbuf[2048];
    __shared__ float red[1024];

    const int tid = threadIdx.x;

    for (int n = tid; n < NPRIOR; n += 1024) {
        instA[n] = g_cls[n]          * 2.0f;   // CLS_W
        instB[n] = g_cls[NPRIOR + n] * 2.0f;
    }
    __syncthreads();

    // focal matched corrections: 768 parallel shared-atomic adds
    if (tid < 2 * SB * LANES) {
        int branch = tid / (SB * LANES);
        int rem    = tid % (SB * LANES);
        int r = g_rows[tid];
        size_t idx = ((size_t)branch * SB + rem / LANES) * NPRIOR + r;
        float corr = (g_cpos[idx] - g_cneg[idx]) * (2.0f / 96.0f);
        atomicAdd(branch == 0 ? &instA[r] : &instB[r], corr);
    }
    // reg/iou: sum over sb, scatter at rows from last (s,b)
    if (tid >= 1016) {                         // 8 threads (avoid overlap w/ above warps)
        int t = tid - 1016;
        int branch = t >> 2, l = t & 3;
        float rs = 0.0f, is = 0.0f;
        #pragma unroll 8
        for (int i = 0; i < SB; i++) {
            rs += g_reg[(branch * SB + i) * LANES + l];
            is += g_iou[(branch * SB + i) * LANES + l];
        }
        float add = rs * (1.0f / 96.0f) * 0.5f + is * (1.0f / 96.0f) * 2.0f;
        int r = g_rows[(branch * SB + (SB - 1)) * LANES + l];
        atomicAdd(branch == 0 ? &instA[r] : &instB[r], add);
    }
    __syncthreads();

    for (int n = tid; n < 2048; n += 1024)
        sbuf[n] = (n < NPRIOR) ? (instA[n] - instB[n]) : INFINITY;
    __syncthreads();

    // bitonic sort ascending (2048 elements)
    for (int k = 2; k <= 2048; k <<= 1) {
        for (int j = k >> 1; j > 0; j >>= 1) {
            for (int i = tid; i < 2048; i += 1024) {
                int ixj = i ^ j;
                if (ixj > i) {
                    bool up = ((i & k) == 0);
                    float a = sbuf[i], c = sbuf[ixj];
                    if ((a > c) == up) { sbuf[i] = c; sbuf[ixj] = a; }
                }
            }
            __syncthreads();
        }
    }

    float delta = 0.5f * (sbuf[999] + sbuf[1000]);   // median of 2000

    float acc = 0.0f;
    for (int n = tid; n < NPRIOR; n += 1024) {
        float dm = (diff[n] + diff[NPRIOR + n] + diff[2 * NPRIOR + n]) * (1.0f / 3.0f);
        acc += (1.0f - dm) * (instA[n] - 0.5f * delta)
             + dm          * (instB[n] + 0.5f * delta);
    }
    red[tid] = acc;
    __syncthreads();
    for (int off = 512; off; off >>= 1) {
        if (tid < off) red[tid] += red[tid + off];
        __syncthreads();
    }
    if (tid == 0) out[0] = red[0];
}

// ---------------------------------------------------------------------------
extern "C" void kernel_launch(void* const* d_in, const int* in_sizes, int n_in,
                              void* d_out, int out_size)
{
    const float* fir  = (const float*)d_in[0];
    const float* sec  = (const float*)d_in[1];
    const float* gt   = (const float*)d_in[2];
    const float* diff = (const float*)d_in[3];
    float* out = (float*)d_out;

    cost_kernel  <<<dim3(SB, NSPLIT, 2), 256>>>(fir, sec, gt);
    assign_kernel<<<dim3(SB, 2),        256>>>(fir, sec, gt);
    cls_kernel   <<<dim3((NPRIOR + 255) / 256, 2), 256>>>();
    final_kernel <<<1, 1024>>>(diff, out);
}